// round 4
// baseline (speedup 1.0000x reference)
#include <cuda_runtime.h>

// out[b, y, x] = in[b, y + dyi[b], x - dxi[b]] if in-bounds else 0
// B=1024, WIN=256, C=1, fp32.
//
// One warp per PAIR of adjacent rows (same batch): 32 lanes x 8 floats x 2 rows.
// dxi/dyi/selector/clamped chunk indices are shared between the two rows, so
// each thread issues 4 independent LDG.128 up front (MLP=4) after one prologue.

static constexpr int WIN = 256;

__device__ __forceinline__ float4 shift_sel(int s, float4 a, float4 b, float4 c_first)
{
    // helper not used; kept minimal. (see inline code below)
    return a;
}

__global__ __launch_bounds__(256) void translation_kernel(
    const float4* __restrict__ in4,
    const float* __restrict__ dx,
    const float* __restrict__ dy,
    float4* __restrict__ out4)
{
    int idx  = blockIdx.x * blockDim.x + threadIdx.x;
    int lane = idx & 31;
    int pair = idx >> 5;              // row pair index
    int b    = pair >> 7;             // 128 pairs per batch
    int y0   = (pair & 127) << 1;     // first row of the pair
    int y1   = y0 + 1;

    int dxi = (int)dx[b];             // trunc toward zero == astype(int32)
    int dyi = (int)dy[b];

    int sy0 = y0 + dyi;
    int sy1 = y1 + dyi;
    bool ok0 = (unsigned)sy0 < (unsigned)WIN;
    bool ok1 = (unsigned)sy1 < (unsigned)WIN;
    int syc0 = ok0 ? sy0 : 0;
    int syc1 = ok1 ? sy1 : 0;

    const float4* src0 = in4 + (((b << 8) | syc0) << 6);
    const float4* src1 = in4 + (((b << 8) | syc1) << 6);

    int x0  = lane << 3;              // first output float index
    int sx0 = x0 - dxi;
    int q0  = sx0 >> 2;
    int s   = sx0 & 3;                // warp-uniform

    int c0 = q0     < 0 ? 0 : (q0     > 63 ? 63 : q0);
    int c1 = q0 + 1 < 0 ? 0 : (q0 + 1 > 63 ? 63 : q0 + 1);

    // 4 independent wide loads
    float4 r0a0 = __ldg(src0 + c0);
    float4 r0a1 = __ldg(src0 + c1);
    float4 r1a0 = __ldg(src1 + c0);
    float4 r1a1 = __ldg(src1 + c1);

    // a2 = next lane's a0 (lane 31 loads its own)
    float4 r0a2, r1a2;
    r0a2.x = __shfl_down_sync(0xffffffffu, r0a0.x, 1);
    r0a2.y = __shfl_down_sync(0xffffffffu, r0a0.y, 1);
    r0a2.z = __shfl_down_sync(0xffffffffu, r0a0.z, 1);
    r0a2.w = __shfl_down_sync(0xffffffffu, r0a0.w, 1);
    r1a2.x = __shfl_down_sync(0xffffffffu, r1a0.x, 1);
    r1a2.y = __shfl_down_sync(0xffffffffu, r1a0.y, 1);
    r1a2.z = __shfl_down_sync(0xffffffffu, r1a0.z, 1);
    r1a2.w = __shfl_down_sync(0xffffffffu, r1a0.w, 1);
    if (lane == 31) {
        int c2 = q0 + 2 < 0 ? 0 : (q0 + 2 > 63 ? 63 : q0 + 2);
        r0a2 = __ldg(src0 + c2);
        r1a2 = __ldg(src1 + c2);
    }

    float4 o00, o01, o10, o11;
    if (s == 0) {
        o00 = r0a0; o01 = r0a1;
        o10 = r1a0; o11 = r1a1;
    } else if (s == 1) {
        o00 = make_float4(r0a0.y, r0a0.z, r0a0.w, r0a1.x);
        o01 = make_float4(r0a1.y, r0a1.z, r0a1.w, r0a2.x);
        o10 = make_float4(r1a0.y, r1a0.z, r1a0.w, r1a1.x);
        o11 = make_float4(r1a1.y, r1a1.z, r1a1.w, r1a2.x);
    } else if (s == 2) {
        o00 = make_float4(r0a0.z, r0a0.w, r0a1.x, r0a1.y);
        o01 = make_float4(r0a1.z, r0a1.w, r0a2.x, r0a2.y);
        o10 = make_float4(r1a0.z, r1a0.w, r1a1.x, r1a1.y);
        o11 = make_float4(r1a1.z, r1a1.w, r1a2.x, r1a2.y);
    } else {
        o00 = make_float4(r0a0.w, r0a1.x, r0a1.y, r0a1.z);
        o01 = make_float4(r0a1.w, r0a2.x, r0a2.y, r0a2.z);
        o10 = make_float4(r1a0.w, r1a1.x, r1a1.y, r1a1.z);
        o11 = make_float4(r1a1.w, r1a2.x, r1a2.y, r1a2.z);
    }

    // per-component edge masking (also kills invalid rows)
    unsigned b0 = ok0 ? (unsigned)sx0 : 0xC0000000u;
    unsigned b1 = ok1 ? (unsigned)sx0 : 0xC0000000u;
    if (b0 + 0u >= (unsigned)WIN) o00.x = 0.f;
    if (b0 + 1u >= (unsigned)WIN) o00.y = 0.f;
    if (b0 + 2u >= (unsigned)WIN) o00.z = 0.f;
    if (b0 + 3u >= (unsigned)WIN) o00.w = 0.f;
    if (b0 + 4u >= (unsigned)WIN) o01.x = 0.f;
    if (b0 + 5u >= (unsigned)WIN) o01.y = 0.f;
    if (b0 + 6u >= (unsigned)WIN) o01.z = 0.f;
    if (b0 + 7u >= (unsigned)WIN) o01.w = 0.f;
    if (b1 + 0u >= (unsigned)WIN) o10.x = 0.f;
    if (b1 + 1u >= (unsigned)WIN) o10.y = 0.f;
    if (b1 + 2u >= (unsigned)WIN) o10.z = 0.f;
    if (b1 + 3u >= (unsigned)WIN) o10.w = 0.f;
    if (b1 + 4u >= (unsigned)WIN) o11.x = 0.f;
    if (b1 + 5u >= (unsigned)WIN) o11.y = 0.f;
    if (b1 + 6u >= (unsigned)WIN) o11.z = 0.f;
    if (b1 + 7u >= (unsigned)WIN) o11.w = 0.f;

    int row0 = (b << 8) | y0;
    float4* dst0 = out4 + (row0 << 6) + (lane << 1);
    float4* dst1 = dst0 + 64;
    dst0[0] = o00;
    dst0[1] = o01;
    dst1[0] = o10;
    dst1[1] = o11;
}

extern "C" void kernel_launch(void* const* d_in, const int* in_sizes, int n_in,
                              void* d_out, int out_size)
{
    const float4* in  = (const float4*)d_in[0];
    const float*  dx  = (const float*)d_in[1];
    const float*  dy  = (const float*)d_in[2];
    float4*       out = (float4*)d_out;

    // warps = B*WIN/2 = 131072 ; threads = 4,194,304
    int threads = 256;
    int blocks  = (1024 * 128 * 32) / threads;   // 16384
    translation_kernel<<<blocks, threads>>>(in, dx, dy, out);
}